// round 3
// baseline (speedup 1.0000x reference)
#include <cuda_runtime.h>
#include <cub/cub.cuh>
#include <thrust/iterator/counting_iterator.h>
#include <thrust/iterator/transform_iterator.h>

// Problem constants (fixed by setup_inputs)
#define BB 4
#define NN 131072
#define BN (BB * NN)          // 524288
// components per point: means 3 + cov 9 + harm 75 + opac 1 = 88

// -------- device scratch (static: no allocations allowed) --------
__device__ unsigned g_min_u, g_max_u;
__device__ unsigned g_keys_in[BN];
__device__ unsigned g_keys_out[BN];
__device__ unsigned g_vals_in[BN];
__device__ unsigned g_vals_out[BN];
__device__ int      g_scan[BN];
__device__ int      g_segstart[BN];  // sorted index of head of segment m (per batch)
__device__ int      g_uniq[BB];
__device__ unsigned char g_temp[32u * 1024u * 1024u]; // cub temp storage

// -------- float <-> order-preserving unsigned --------
__device__ __forceinline__ unsigned f2ord(float f) {
    unsigned u = __float_as_uint(f);
    return (u & 0x80000000u) ? ~u : (u | 0x80000000u);
}
__device__ __forceinline__ float ord2f(unsigned u) {
    return __uint_as_float((u & 0x80000000u) ? (u & 0x7fffffffu) : ~u);
}

__global__ void k_init() {
    g_min_u = 0xFFFFFFFFu;
    g_max_u = 0u;
}

// Vectorized min/max over means (BN*3 floats, divisible by 4).
__global__ void k_minmax(const float4* __restrict__ means4) {
    unsigned lo = 0xFFFFFFFFu, hi = 0u;
    for (int i = blockIdx.x * blockDim.x + threadIdx.x; i < BN * 3 / 4;
         i += gridDim.x * blockDim.x) {
        float4 v = __ldg(&means4[i]);
        unsigned o0 = f2ord(v.x), o1 = f2ord(v.y), o2 = f2ord(v.z), o3 = f2ord(v.w);
        lo = min(min(lo, o0), min(o1, min(o2, o3)));
        hi = max(max(hi, o0), max(o1, max(o2, o3)));
    }
#pragma unroll
    for (int s = 16; s; s >>= 1) {
        lo = min(lo, __shfl_xor_sync(0xFFFFFFFFu, lo, s));
        hi = max(hi, __shfl_xor_sync(0xFFFFFFFFu, hi, s));
    }
    if ((threadIdx.x & 31) == 0) {
        atomicMin(&g_min_u, lo);
        atomicMax(&g_max_u, hi);
    }
}

// Build 32-bit sort keys: (batch<<30) | linear voxel id  (lin < 1e9 < 2^30).
// Float math forced to IEEE RN so fast-math flags cannot flip floor() results.
__global__ void k_keys(const float* __restrict__ means) {
    int p = blockIdx.x * blockDim.x + threadIdx.x;
    if (p >= BN) return;
    float mmin = ord2f(g_min_u);
    float mmax = ord2f(g_max_u);
    float rng = __fsub_rn(mmax, mmin);
    long long vn = (long long)floorf(__fdiv_rn(rng, 0.001f)) + 1;
    if (vn > 1000) vn = 1000;
    if (vn < 1) vn = 1;
    float vnf = (float)vn;
    float den = __fadd_rn(rng, 1e-6f);
    unsigned lin = 0;
#pragma unroll
    for (int d = 0; d < 3; ++d) {
        float m = __ldg(&means[p * 3 + d]);
        float nrm = __fdiv_rn(__fsub_rn(m, mmin), den);
        long long v = (long long)floorf(__fmul_rn(nrm, vnf));
        if (v < 0) v = 0;
        if (v > vn - 1) v = vn - 1;
        lin = lin * (unsigned)vn + (unsigned)v;
    }
    unsigned b = (unsigned)(p / NN);
    g_keys_in[p] = (b << 30) | lin;
    g_vals_in[p] = (unsigned)p;
}

// Flag functor for the fused scan: flag(i) = new-segment indicator.
struct FlagOp {
    const unsigned* keys;
    __host__ __device__ __forceinline__ int operator()(int i) const {
        return (i % NN != 0) && (keys[i] != keys[i - 1]);
    }
};

// After scan: segment heads record sorted start index at rank slot; record uniq.
__global__ void k_heads() {
    int i = blockIdx.x * blockDim.x + threadIdx.x;
    if (i >= BN) return;
    int b = i / NN;
    if ((i + 1) % NN == 0) g_uniq[b] = g_scan[i] - g_scan[b * NN] + 1;
    bool head = (i % NN == 0) || (g_keys_out[i - 1] != g_keys_out[i]);
    if (head) {
        int m = g_scan[i] - g_scan[b * NN];  // dense rank within batch
        g_segstart[b * NN + m] = i;
    }
}

// Phase B: one WARP per output row. Lane l owns unified components
// {l, l+32, l+64} of the 88 per-row components:
//   [0,3) means, [3,12) cov, [12,87) harm, 87 opac.
// Singleton segments (the common case) never touch scores (w = 1).
// Rows >= uniq store zeros (acc stays 0). All loads/stores lane-contiguous.
__global__ __launch_bounds__(256) void k_phaseB(
    const float* __restrict__ scores, const float* __restrict__ means,
    const float* __restrict__ cov, const float* __restrict__ harm,
    const float* __restrict__ opac, float* __restrict__ out) {
    int r = blockIdx.x * 8 + (threadIdx.x >> 5);  // global row
    int lane = threadIdx.x & 31;
    int b = r >> 17;          // r / NN
    int m = r & (NN - 1);     // r % NN
    int uniq = g_uniq[b];

    float a0 = 0.0f, a1 = 0.0f, a2 = 0.0f;
    int c0 = lane, c1 = lane + 32, c2 = lane + 64;  // c2 valid for lane < 24

    if (m < uniq) {
        int start = g_segstart[b * NN + m];
        int end = (m + 1 < uniq) ? g_segstart[b * NN + m + 1] : (b + 1) * NN;
        int cnt = end - start;

        float mx = 0.0f, den = 1.0f;
        if (cnt > 1) {
            // softmax stats via strided warp loop + reductions (any cnt)
            mx = __int_as_float(0xff800000);
            for (int j = start + lane; j < end; j += 32)
                mx = fmaxf(mx, __ldg(&scores[g_vals_out[j]]));
#pragma unroll
            for (int s = 16; s; s >>= 1)
                mx = fmaxf(mx, __shfl_xor_sync(0xFFFFFFFFu, mx, s));
            den = 0.0f;
            for (int j = start + lane; j < end; j += 32)
                den += expf(__ldg(&scores[g_vals_out[j]]) - mx);
#pragma unroll
            for (int s = 16; s; s >>= 1)
                den += __shfl_xor_sync(0xFFFFFFFFu, den, s);
        }

        for (int j = start; j < end; ++j) {
            int p = (int)g_vals_out[j];
            float w = 1.0f;
            if (cnt > 1)
                w = expf(__ldg(&scores[p]) - mx) / den;  // broadcast load

            // slot 0: c0 in [0,32): means/cov/harm head
            float v0;
            if (c0 < 3)       v0 = __ldg(&means[p * 3 + c0]);
            else if (c0 < 12) v0 = __ldg(&cov[p * 9 + (c0 - 3)]);
            else              v0 = __ldg(&harm[p * 75 + (c0 - 12)]);
            a0 = fmaf(w, v0, a0);

            // slot 1: c1 in [32,64): all harm
            a1 = fmaf(w, __ldg(&harm[p * 75 + (c1 - 12)]), a1);

            // slot 2: c2 in [64,88): harm tail + opac (lane < 24)
            if (lane < 24) {
                float v2 = (c2 == 87) ? __ldg(&opac[p])
                                      : __ldg(&harm[p * 75 + (c2 - 12)]);
                a2 = fmaf(w, v2, a2);
            }
        }
    }

    float* out_means = out;
    float* out_cov   = out + (size_t)3 * BN;
    float* out_harm  = out + (size_t)12 * BN;
    float* out_opac  = out + (size_t)87 * BN;

    // slot 0 stores
    if (c0 < 3)       out_means[(size_t)r * 3 + c0] = a0;
    else if (c0 < 12) out_cov[(size_t)r * 9 + (c0 - 3)] = a0;
    else              out_harm[(size_t)r * 75 + (c0 - 12)] = a0;
    // slot 1
    out_harm[(size_t)r * 75 + (c1 - 12)] = a1;
    // slot 2
    if (lane < 24) {
        if (c2 == 87) out_opac[r] = a2;
        else          out_harm[(size_t)r * 75 + (c2 - 12)] = a2;
    }
}

extern "C" void kernel_launch(void* const* d_in, const int* in_sizes, int n_in,
                              void* d_out, int out_size) {
    const float* scores = (const float*)d_in[0];  // [B,N,1]
    const float* means  = (const float*)d_in[1];  // [B,N,3]
    const float* cov    = (const float*)d_in[2];  // [B,N,3,3]
    const float* harm   = (const float*)d_in[3];  // [B,N,3,25]
    const float* opac   = (const float*)d_in[4];  // [B,N]
    float* out = (float*)d_out;

    void *pki, *pko, *pvi, *pvo, *pscan, *ptemp;
    cudaGetSymbolAddress(&pki, g_keys_in);
    cudaGetSymbolAddress(&pko, g_keys_out);
    cudaGetSymbolAddress(&pvi, g_vals_in);
    cudaGetSymbolAddress(&pvo, g_vals_out);
    cudaGetSymbolAddress(&pscan, g_scan);
    cudaGetSymbolAddress(&ptemp, g_temp);

    k_init<<<1, 32>>>();
    k_minmax<<<512, 256>>>((const float4*)means);
    k_keys<<<BN / 256, 256>>>(means);

    size_t tmp_bytes = 0;
    cub::DeviceRadixSort::SortPairs(nullptr, tmp_bytes,
                                    (const unsigned*)pki, (unsigned*)pko,
                                    (const unsigned*)pvi, (unsigned*)pvo,
                                    BN, 0, 32);
    if (tmp_bytes > sizeof(g_temp)) tmp_bytes = sizeof(g_temp);
    cub::DeviceRadixSort::SortPairs(ptemp, tmp_bytes,
                                    (const unsigned*)pki, (unsigned*)pko,
                                    (const unsigned*)pvi, (unsigned*)pvo,
                                    BN, 0, 32);

    // Fused flags + inclusive scan (no materialized flag array / extra kernel)
    FlagOp fop{(const unsigned*)pko};
    auto fit = thrust::make_transform_iterator(
        thrust::make_counting_iterator<int>(0), fop);
    size_t tmp2 = 0;
    cub::DeviceScan::InclusiveSum(nullptr, tmp2, fit, (int*)pscan, BN);
    if (tmp2 > sizeof(g_temp)) tmp2 = sizeof(g_temp);
    cub::DeviceScan::InclusiveSum(ptemp, tmp2, fit, (int*)pscan, BN);

    k_heads<<<BN / 256, 256>>>();
    k_phaseB<<<BN / 8, 256>>>(scores, means, cov, harm, opac, out);
}

// round 4
// speedup vs baseline: 1.3183x; 1.3183x over previous
#include <cuda_runtime.h>
#include <cub/cub.cuh>
#include <thrust/iterator/counting_iterator.h>
#include <thrust/iterator/transform_iterator.h>

// Problem constants (fixed by setup_inputs)
#define BB 4
#define NN 131072
#define BN (BB * NN)          // 524288
// components per point: means 3 + cov 9 + harm 75 + opac 1 = 88

// -------- device scratch (static: no allocations allowed) --------
__device__ unsigned g_min_u, g_max_u;
__device__ unsigned g_keys_in[BN];
__device__ unsigned g_keys_out[BN];
__device__ unsigned g_vals_in[BN];
__device__ unsigned g_vals_out[BN];
__device__ int      g_scan[BN];
__device__ int      g_segstart[BN];  // sorted index of head of segment m (per batch)
__device__ int      g_uniq[BB];
__device__ unsigned char g_temp[32u * 1024u * 1024u]; // cub temp storage

// -------- float <-> order-preserving unsigned --------
__device__ __forceinline__ unsigned f2ord(float f) {
    unsigned u = __float_as_uint(f);
    return (u & 0x80000000u) ? ~u : (u | 0x80000000u);
}
__device__ __forceinline__ float ord2f(unsigned u) {
    return __uint_as_float((u & 0x80000000u) ? (u & 0x7fffffffu) : ~u);
}

__global__ void k_init() {
    g_min_u = 0xFFFFFFFFu;
    g_max_u = 0u;
}

// Vectorized min/max over means (BN*3 floats, divisible by 4).
__global__ void k_minmax(const float4* __restrict__ means4) {
    unsigned lo = 0xFFFFFFFFu, hi = 0u;
    for (int i = blockIdx.x * blockDim.x + threadIdx.x; i < BN * 3 / 4;
         i += gridDim.x * blockDim.x) {
        float4 v = __ldg(&means4[i]);
        unsigned o0 = f2ord(v.x), o1 = f2ord(v.y), o2 = f2ord(v.z), o3 = f2ord(v.w);
        lo = min(min(lo, o0), min(o1, min(o2, o3)));
        hi = max(max(hi, o0), max(o1, max(o2, o3)));
    }
#pragma unroll
    for (int s = 16; s; s >>= 1) {
        lo = min(lo, __shfl_xor_sync(0xFFFFFFFFu, lo, s));
        hi = max(hi, __shfl_xor_sync(0xFFFFFFFFu, hi, s));
    }
    if ((threadIdx.x & 31) == 0) {
        atomicMin(&g_min_u, lo);
        atomicMax(&g_max_u, hi);
    }
}

// Build 32-bit sort keys: (batch<<30) | linear voxel id  (lin < 1e9 < 2^30).
// Float math forced to IEEE RN so fast-math flags cannot flip floor() results.
__global__ void k_keys(const float* __restrict__ means) {
    int p = blockIdx.x * blockDim.x + threadIdx.x;
    if (p >= BN) return;
    float mmin = ord2f(g_min_u);
    float mmax = ord2f(g_max_u);
    float rng = __fsub_rn(mmax, mmin);
    long long vn = (long long)floorf(__fdiv_rn(rng, 0.001f)) + 1;
    if (vn > 1000) vn = 1000;
    if (vn < 1) vn = 1;
    float vnf = (float)vn;
    float den = __fadd_rn(rng, 1e-6f);
    unsigned lin = 0;
#pragma unroll
    for (int d = 0; d < 3; ++d) {
        float m = __ldg(&means[p * 3 + d]);
        float nrm = __fdiv_rn(__fsub_rn(m, mmin), den);
        long long v = (long long)floorf(__fmul_rn(nrm, vnf));
        if (v < 0) v = 0;
        if (v > vn - 1) v = vn - 1;
        lin = lin * (unsigned)vn + (unsigned)v;
    }
    unsigned b = (unsigned)(p / NN);
    g_keys_in[p] = (b << 30) | lin;
    g_vals_in[p] = (unsigned)p;
}

// Flag functor for the fused scan: flag(i) = new-segment indicator.
struct FlagOp {
    const unsigned* keys;
    __host__ __device__ __forceinline__ int operator()(int i) const {
        return (i % NN != 0) && (keys[i] != keys[i - 1]);
    }
};

// After scan: segment heads record sorted start index at rank slot; record uniq.
__global__ void k_heads() {
    int i = blockIdx.x * blockDim.x + threadIdx.x;
    if (i >= BN) return;
    int b = i / NN;
    if ((i + 1) % NN == 0) g_uniq[b] = g_scan[i] - g_scan[b * NN] + 1;
    bool head = (i % NN == 0) || (g_keys_out[i - 1] != g_keys_out[i]);
    if (head) {
        int m = g_scan[i] - g_scan[b * NN];  // dense rank within batch
        g_segstart[b * NN + m] = i;
    }
}

// Phase B: 32 rows per 256-thread block, 8 threads per row (4 rows/warp so
// every load instruction serves 4 points). Register accumulators; one shared
// staging pass at the end feeds fully-coalesced contiguous output stores.
// Component ownership of thread tx (0..7) within its row:
//   means: tx<3          cov: tx and (tx==0 ? 8 : -)   opac: tx==0
//   harm:  tx+8k, k=0..8 and (tx<3 ? tx+72 : -)
// Singleton segments (the overwhelming case) never touch scores (w = 1).
// Rows >= uniq keep zero accumulators -> zero-padded tail for free.
__global__ __launch_bounds__(256) void k_phaseB(
    const float* __restrict__ scores, const float* __restrict__ means,
    const float* __restrict__ cov, const float* __restrict__ harm,
    const float* __restrict__ opac, float* __restrict__ out) {
    __shared__ float acc[32][89];  // 88 comps + pad

    int t = threadIdx.x;
    int r0 = blockIdx.x * 32;       // NN % 32 == 0 -> one batch per block
    int b = r0 >> 17;               // r0 / NN
    int uniq = g_uniq[b];
    int row = t >> 3;
    int tx = t & 7;
    int m = (r0 & (NN - 1)) + row;

    float am = 0.0f, ac0 = 0.0f, ac1 = 0.0f, ao = 0.0f;
    float ah[10];
#pragma unroll
    for (int k = 0; k < 10; ++k) ah[k] = 0.0f;

    if (m < uniq) {
        int base = b * NN;
        int start = g_segstart[base + m];
        int end = (m + 1 < uniq) ? g_segstart[base + m + 1] : base + NN;
        int cnt = end - start;

        float mx = 0.0f, den = 1.0f;
        if (cnt > 1) {
            unsigned gmask = 0xFFu << (t & 24);  // this thread's 8-lane group
            mx = __int_as_float(0xff800000);     // -inf
            for (int j = start + tx; j < end; j += 8)
                mx = fmaxf(mx, __ldg(&scores[g_vals_out[j]]));
#pragma unroll
            for (int s = 4; s; s >>= 1)
                mx = fmaxf(mx, __shfl_xor_sync(gmask, mx, s));
            den = 0.0f;
            for (int j = start + tx; j < end; j += 8)
                den += expf(__ldg(&scores[g_vals_out[j]]) - mx);
#pragma unroll
            for (int s = 4; s; s >>= 1)
                den += __shfl_xor_sync(gmask, den, s);
        }

        for (int j = start; j < end; ++j) {
            int p = (int)g_vals_out[j];
            float w = 1.0f;
            if (cnt > 1)
                w = expf(__ldg(&scores[p]) - mx) / den;  // broadcast load

            if (tx < 3) am = fmaf(w, __ldg(&means[p * 3 + tx]), am);
            ac0 = fmaf(w, __ldg(&cov[p * 9 + tx]), ac0);
            if (tx == 0) ac1 = fmaf(w, __ldg(&cov[p * 9 + 8]), ac1);
            const float* hrow = harm + (size_t)p * 75;
#pragma unroll
            for (int k = 0; k < 9; ++k)
                ah[k] = fmaf(w, __ldg(&hrow[tx + 8 * k]), ah[k]);
            if (tx < 3) ah[9] = fmaf(w, __ldg(&hrow[tx + 72]), ah[9]);
            if (tx == 0) ao = fmaf(w, __ldg(&opac[p]), ao);
        }
    }

    // Spill registers to shared (every one of the 88 cells is written,
    // zeros included, so no separate zero-init pass is needed).
    if (tx < 3) acc[row][tx] = am;            // means -> cols 0..2
    acc[row][3 + tx] = ac0;                   // cov 0..7 -> cols 3..10
    if (tx == 0) acc[row][11] = ac1;          // cov 8 -> col 11
#pragma unroll
    for (int k = 0; k < 9; ++k)
        acc[row][12 + tx + 8 * k] = ah[k];    // harm 0..71 -> cols 12..83
    if (tx < 3) acc[row][84 + tx] = ah[9];    // harm 72..74 -> cols 84..86
    if (tx == 0) acc[row][87] = ao;           // opac -> col 87
    __syncthreads();

    float* out_means = out;
    float* out_cov   = out + (size_t)3 * BN;
    float* out_harm  = out + (size_t)12 * BN;
    float* out_opac  = out + (size_t)87 * BN;

    if (t < 96) out_means[(size_t)r0 * 3 + t] = acc[t / 3][t % 3];
    for (int idx = t; idx < 288; idx += 256)
        out_cov[(size_t)r0 * 9 + idx] = acc[idx / 9][3 + idx % 9];
    for (int idx = t; idx < 2400; idx += 256)
        out_harm[(size_t)r0 * 75 + idx] = acc[idx / 75][12 + idx % 75];
    if (t < 32) out_opac[r0 + t] = acc[t][87];
}

extern "C" void kernel_launch(void* const* d_in, const int* in_sizes, int n_in,
                              void* d_out, int out_size) {
    const float* scores = (const float*)d_in[0];  // [B,N,1]
    const float* means  = (const float*)d_in[1];  // [B,N,3]
    const float* cov    = (const float*)d_in[2];  // [B,N,3,3]
    const float* harm   = (const float*)d_in[3];  // [B,N,3,25]
    const float* opac   = (const float*)d_in[4];  // [B,N]
    float* out = (float*)d_out;

    void *pki, *pko, *pvi, *pvo, *pscan, *ptemp;
    cudaGetSymbolAddress(&pki, g_keys_in);
    cudaGetSymbolAddress(&pko, g_keys_out);
    cudaGetSymbolAddress(&pvi, g_vals_in);
    cudaGetSymbolAddress(&pvo, g_vals_out);
    cudaGetSymbolAddress(&pscan, g_scan);
    cudaGetSymbolAddress(&ptemp, g_temp);

    k_init<<<1, 32>>>();
    k_minmax<<<512, 256>>>((const float4*)means);
    k_keys<<<BN / 256, 256>>>(means);

    size_t tmp_bytes = 0;
    cub::DeviceRadixSort::SortPairs(nullptr, tmp_bytes,
                                    (const unsigned*)pki, (unsigned*)pko,
                                    (const unsigned*)pvi, (unsigned*)pvo,
                                    BN, 0, 32);
    if (tmp_bytes > sizeof(g_temp)) tmp_bytes = sizeof(g_temp);
    cub::DeviceRadixSort::SortPairs(ptemp, tmp_bytes,
                                    (const unsigned*)pki, (unsigned*)pko,
                                    (const unsigned*)pvi, (unsigned*)pvo,
                                    BN, 0, 32);

    // Fused flags + inclusive scan (no materialized flag array / extra kernel)
    FlagOp fop{(const unsigned*)pko};
    auto fit = thrust::make_transform_iterator(
        thrust::make_counting_iterator<int>(0), fop);
    size_t tmp2 = 0;
    cub::DeviceScan::InclusiveSum(nullptr, tmp2, fit, (int*)pscan, BN);
    if (tmp2 > sizeof(g_temp)) tmp2 = sizeof(g_temp);
    cub::DeviceScan::InclusiveSum(ptemp, tmp2, fit, (int*)pscan, BN);

    k_heads<<<BN / 256, 256>>>();
    k_phaseB<<<BN / 32, 256>>>(scores, means, cov, harm, opac, out);
}